// round 17
// baseline (speedup 1.0000x reference)
#include <cuda_runtime.h>
#include <cuda_fp16.h>
#include <cstdint>

#define HIDDEN 1024
#define NCOLS 1858
#define NROWS_PM 4288
#define MAXB 2048
#define NSEG 16

// ---------------- scratch (device globals: allocation-free) ----------------
__device__ __half g_HSh[(size_t)MAXB * 64 * HIDDEN]; // HS in fp16
__device__ __half g_Mh[HIDDEN * HIDDEN];             // M^T in fp16 (n rows, k contiguous)
__device__ float  g_Mp[16][HIDDEN * HIDDEN];         // split-K partials for M
__device__ float  g_Weff[3 * HIDDEN];
__device__ float  g_PO[MAXB * 24];
__device__ int    g_cnt[NCOLS];
__device__ int    g_rows[NCOLS * 16];
__device__ int    g_cntS[NSEG * NCOLS];
__device__ int    g_rowsS[NSEG * NCOLS * 8];

// ---------------- PTX helpers (arch-agnostic: sm_80+ only) -----------------
__device__ __forceinline__ uint32_t smem_u32(const void* p) {
    uint32_t a;
    asm("{ .reg .u64 t; cvta.to.shared.u64 t, %1; cvt.u32.u64 %0, t; }" : "=r"(a) : "l"(p));
    return a;
}
__device__ __forceinline__ void cp_async16(uint32_t s, const void* g) {
    asm volatile("cp.async.cg.shared.global [%0], [%1], 16;" :: "r"(s), "l"(g));
}
#define CP_COMMIT() asm volatile("cp.async.commit_group;" ::: "memory")
#define CP_WAIT1() asm volatile("cp.async.wait_group 1;" ::: "memory")
#define CP_WAIT0() asm volatile("cp.async.wait_group 0;" ::: "memory")

__device__ __forceinline__ void mma_f16(float* c, const uint32_t* a, const uint32_t* b) {
    asm volatile(
        "mma.sync.aligned.m16n8k16.row.col.f32.f16.f16.f32 "
        "{%0,%1,%2,%3}, {%4,%5,%6,%7}, {%8,%9}, {%0,%1,%2,%3};"
        : "+f"(c[0]), "+f"(c[1]), "+f"(c[2]), "+f"(c[3])
        : "r"(a[0]), "r"(a[1]), "r"(a[2]), "r"(a[3]), "r"(b[0]), "r"(b[1]));
}
__device__ __forceinline__ void ldm_x4(uint32_t* r, uint32_t addr) {
    asm volatile("ldmatrix.sync.aligned.m8n8.x4.shared.b16 {%0,%1,%2,%3}, [%4];"
        : "=r"(r[0]), "=r"(r[1]), "=r"(r[2]), "=r"(r[3]) : "r"(addr));
}
__device__ __forceinline__ uint32_t pack_h2(float x, float y) {
    __half2 h = __floats2half2_rn(x, y);
    return *(uint32_t*)&h;
}
// swizzled byte offset within a [rows x 32half] tile (row stride 64B)
__device__ __forceinline__ uint32_t swz(int row, int ku) {
    return (uint32_t)(row * 64 + ((ku ^ ((row >> 1) & 3)) << 4));
}

// ---------------- preround segment: HS fp32 -> g_HSh fp16 ------------------
__global__ __launch_bounds__(256) void preround_hs(const float* __restrict__ HS,
                                                   int base4, int n4) {
    int i = blockIdx.x * blockDim.x + threadIdx.x;
    if (i >= n4) return;
    int gi = base4 + i;
    float4 v = ((const float4*)HS)[gi];
    uint2 w;
    w.x = pack_h2(v.x, v.y);
    w.y = pack_h2(v.z, v.w);
    ((uint2*)g_HSh)[gi] = w;
}

// ---------------- Fused pass1+pass2, n-split as inner loop -----------------
#define P1_STAGEB 24576
#define HSN_B 73728
#define TST_B 141312
#define P1_SMEMB 208896

__global__ __launch_bounds__(256, 1) void pass1_mma(float* __restrict__ PA, int m_off) {
    extern __shared__ __half hsm[];
    uint32_t sb = smem_u32(hsm);
    int tid = threadIdx.x, wid = tid >> 5, lane = tid & 31;
    int wm = wid >> 2, wn = wid & 3;
    int lr = lane >> 2, lc = lane & 3;
    int g = lane >> 3, tr = lane & 7;
    int mby = m_off + blockIdx.x;
    int m_base = mby * 128;
    const __half* Ag = g_HSh + (size_t)m_base * HIDDEN;

    int wb = wid >> 2;
    int wq = wid & 3;
    int wy = wq >> 1, wx = wq & 1;
    float acc2[2][4][4];
#pragma unroll
    for (int i = 0; i < 2; i++)
#pragma unroll
        for (int j = 0; j < 4; j++)
#pragma unroll
            for (int t = 0; t < 4; t++) acc2[i][j][t] = 0.0f;

    for (int s = 0; s < 4; s++) {
        int n_base = s * 256;
        if (s > 0) __syncthreads();

        // HSn tile
#pragma unroll
        for (int it = 0; it < 16; it++) {
            int idx = tid + it * 256;
            int row = idx >> 5, seg = idx & 31;
            cp_async16(sb + HSN_B + row * 528 + seg * 16,
                       Ag + (size_t)row * HIDDEN + n_base + seg * 8);
        }
        CP_COMMIT();

        auto prefetch = [&](int chunk, int stg) {
            int k0 = chunk * 32;
            uint32_t base = sb + stg * P1_STAGEB;
#pragma unroll
            for (int it = 0; it < 2; it++) {
                int idx = tid + it * 256;
                int r = idx >> 2, seg = idx & 3;
                cp_async16(base + swz(r, seg), Ag + (size_t)r * HIDDEN + k0 + seg * 8);
            }
#pragma unroll
            for (int it = 0; it < 4; it++) {
                int idx = tid + it * 256;
                int r = idx >> 2, seg = idx & 3;
                cp_async16(base + 8192 + swz(r, seg),
                           g_Mh + (size_t)(n_base + r) * HIDDEN + k0 + seg * 8);
            }
        };

        float acc[4][8][4];
#pragma unroll
        for (int i = 0; i < 4; i++)
#pragma unroll
            for (int j = 0; j < 8; j++)
#pragma unroll
                for (int t = 0; t < 4; t++) acc[i][j][t] = 0.0f;

        prefetch(0, 0); CP_COMMIT();
        prefetch(1, 1); CP_COMMIT();

        int stg = 0;
        for (int c = 0; c < 32; c++) {
            if (c < 31) { CP_WAIT1(); } else { CP_WAIT0(); }
            __syncthreads();
            if (c < 30) {
                int ns = stg + 2; if (ns >= 3) ns -= 3;
                prefetch(c + 2, ns);
                CP_COMMIT();
            }
            uint32_t sA = sb + stg * P1_STAGEB;
            uint32_t sB = sA + 8192;
#pragma unroll
            for (int ks = 0; ks < 2; ks++) {
                uint32_t a[4][4], b[8][2];
#pragma unroll
                for (int mi = 0; mi < 4; mi++) {
                    int rr = wm * 64 + mi * 16 + ((g & 1) << 3) + tr;
                    int ku = ks * 2 + (g >> 1);
                    ldm_x4(a[mi], sA + swz(rr, ku));
                }
#pragma unroll
                for (int jj = 0; jj < 8; jj += 2) {
                    int rr = wn * 64 + (jj + (g >> 1)) * 8 + tr;
                    int ku = ks * 2 + (g & 1);
                    uint32_t r4[4];
                    ldm_x4(r4, sB + swz(rr, ku));
                    b[jj][0] = r4[0]; b[jj][1] = r4[1];
                    b[jj + 1][0] = r4[2]; b[jj + 1][1] = r4[3];
                }
#pragma unroll
                for (int mi = 0; mi < 4; mi++)
#pragma unroll
                    for (int ni = 0; ni < 8; ni++)
                        mma_f16(acc[mi][ni], a[mi], b[ni]);
            }
            if (++stg == 3) stg = 0;
        }

        // stage T_tile -> smem (fp16)
#pragma unroll
        for (int mi = 0; mi < 4; mi++) {
            int r0 = wm * 64 + mi * 16 + lr;
#pragma unroll
            for (int ni = 0; ni < 8; ni++) {
                int col = wn * 64 + ni * 8 + lc * 2;
                *(uint32_t*)((char*)hsm + TST_B + r0 * 528 + col * 2) =
                    pack_h2(acc[mi][ni][0], acc[mi][ni][1]);
                *(uint32_t*)((char*)hsm + TST_B + (r0 + 8) * 528 + col * 2) =
                    pack_h2(acc[mi][ni][2], acc[mi][ni][3]);
            }
        }
        __syncthreads();

        // MMA2 accumulate
#pragma unroll
        for (int k2 = 0; k2 < 16; k2++) {
            uint32_t a2[2][4], b2[4][2];
#pragma unroll
            for (int mi = 0; mi < 2; mi++) {
                int rr = wb * 64 + wy * 32 + mi * 16 + ((g & 1) << 3) + tr;
                int ku = k2 * 2 + (g >> 1);
                ldm_x4(a2[mi], sb + TST_B + rr * 528 + ku * 16);
            }
#pragma unroll
            for (int jj = 0; jj < 4; jj += 2) {
                int rr = wb * 64 + wx * 32 + (jj + (g >> 1)) * 8 + tr;
                int ku = k2 * 2 + (g & 1);
                uint32_t r4[4];
                ldm_x4(r4, sb + HSN_B + rr * 528 + ku * 16);
                b2[jj][0] = r4[0]; b2[jj][1] = r4[1];
                b2[jj + 1][0] = r4[2]; b2[jj + 1][1] = r4[3];
            }
#pragma unroll
            for (int mi = 0; mi < 2; mi++)
#pragma unroll
                for (int ni = 0; ni < 4; ni++)
                    mma_f16(acc2[mi][ni], a2[mi], b2[ni]);
        }
    }

    // write PA once, scaled by 1/128
    const float sc = 1.0f / 128.0f;
    int board = mby * 2 + wb;
    float* pa = PA + (size_t)board * 4096;
#pragma unroll
    for (int mi = 0; mi < 2; mi++) {
        int r = wy * 32 + mi * 16 + lr;
#pragma unroll
        for (int ni = 0; ni < 4; ni++) {
            int col = wx * 32 + ni * 8 + lc * 2;
            *(float2*)&pa[r * 64 + col] =
                make_float2(acc2[mi][ni][0] * sc, acc2[mi][ni][1] * sc);
            *(float2*)&pa[(r + 8) * 64 + col] =
                make_float2(acc2[mi][ni][2] * sc, acc2[mi][ni][3] * sc);
        }
    }
}

// ---------------- colmap: 16-segment parallel build + ordered merge --------
__global__ void build_colmap_seg(const float* __restrict__ pm) {
    int c = blockIdx.x * blockDim.x + threadIdx.x;
    int seg = blockIdx.y;
    if (c >= NCOLS) return;
    int r0 = seg * 268, r1 = r0 + 268;
    if (r1 > NROWS_PM) r1 = NROWS_PM;
    int n = 0;
    for (int r = r0; r < r1; r++) {
        if (pm[(size_t)r * NCOLS + c] != 0.0f) {
            if (n < 8) g_rowsS[(seg * NCOLS + c) * 8 + n] = r;
            n++;
        }
    }
    g_cntS[seg * NCOLS + c] = (n > 8) ? 8 : n;
}
__global__ void merge_colmap() {
    int c = blockIdx.x * blockDim.x + threadIdx.x;
    if (c >= NCOLS) return;
    int n = 0;
    for (int seg = 0; seg < NSEG; seg++) {
        int m = g_cntS[seg * NCOLS + c];
        for (int t = 0; t < m && n < 16; t++)
            g_rows[c * 16 + n++] = g_rowsS[(seg * NCOLS + c) * 8 + t];
    }
    g_cnt[c] = n;
}

// ---------------- g_M partials: split-K x16, deterministic -----------------
__global__ __launch_bounds__(256) void gemm_tn_part(
    const float* __restrict__ A, const float* __restrict__ B) {
    __shared__ float As[8][128];
    __shared__ float Bs[8][128];
    int bi = blockIdx.y, bj = blockIdx.x, ks = blockIdx.z;
    int tid = threadIdx.x;
    int lrow = tid >> 5;
    int lcol = (tid & 31) * 4;
    int tx = tid & 15, ty = tid >> 4;
    int kbase = ks * 64;
    const float* Ap = A + (size_t)(kbase + lrow) * HIDDEN + bi * 128 + lcol;
    const float* Bp = B + (size_t)(kbase + lrow) * HIDDEN + bj * 128 + lcol;
    float acc[8][8];
#pragma unroll
    for (int i = 0; i < 8; i++)
#pragma unroll
        for (int j = 0; j < 8; j++) acc[i][j] = 0.0f;
    for (int k0 = 0; k0 < 64; k0 += 8) {
        *(float4*)&As[lrow][lcol] = *(const float4*)(Ap + (size_t)k0 * HIDDEN);
        *(float4*)&Bs[lrow][lcol] = *(const float4*)(Bp + (size_t)k0 * HIDDEN);
        __syncthreads();
#pragma unroll
        for (int k = 0; k < 8; k++) {
            float a[8], b[8];
            *(float4*)&a[0] = *(float4*)&As[k][ty * 4];
            *(float4*)&a[4] = *(float4*)&As[k][64 + ty * 4];
            *(float4*)&b[0] = *(float4*)&Bs[k][tx * 4];
            *(float4*)&b[4] = *(float4*)&Bs[k][64 + tx * 4];
#pragma unroll
            for (int i = 0; i < 8; i++)
#pragma unroll
                for (int j = 0; j < 8; j++) acc[i][j] += a[i] * b[j];
        }
        __syncthreads();
    }
    float* Mout = g_Mp[ks];
#pragma unroll
    for (int ih = 0; ih < 2; ih++)
#pragma unroll
        for (int i = 0; i < 4; i++) {
            int row = bi * 128 + ih * 64 + ty * 4 + i;
#pragma unroll
            for (int jh = 0; jh < 2; jh++) {
                float4 v = make_float4(acc[ih * 4 + i][jh * 4 + 0], acc[ih * 4 + i][jh * 4 + 1],
                                       acc[ih * 4 + i][jh * 4 + 2], acc[ih * 4 + i][jh * 4 + 3]);
                *(float4*)&Mout[(size_t)row * HIDDEN + bj * 128 + jh * 64 + tx * 4] = v;
            }
        }
}
__global__ __launch_bounds__(256) void mh_combine() {
    int i = blockIdx.x * blockDim.x + threadIdx.x;
    if (i >= HIDDEN * HIDDEN) return;
    float s0 = (g_Mp[0][i] + g_Mp[1][i]) + (g_Mp[2][i] + g_Mp[3][i]);
    float s1 = (g_Mp[4][i] + g_Mp[5][i]) + (g_Mp[6][i] + g_Mp[7][i]);
    float s2 = (g_Mp[8][i] + g_Mp[9][i]) + (g_Mp[10][i] + g_Mp[11][i]);
    float s3 = (g_Mp[12][i] + g_Mp[13][i]) + (g_Mp[14][i] + g_Mp[15][i]);
    g_Mh[i] = __float2half_rn((s0 + s1) + (s2 + s3));
}

// ---------------- Weff: single kernel, no atomics (grid 3x4) ---------------
__global__ void weff_kernel(const float* __restrict__ Wpo, const float* __restrict__ Wpk) {
    int i = blockIdx.x;
    int jseg = blockIdx.y;
    int tid = threadIdx.x;
    int col = jseg * 256 + tid;
    float acc = 0.0f;
    for (int c = 0; c < HIDDEN; c++)
        acc += Wpo[i * HIDDEN + c] * Wpk[(size_t)c * HIDDEN + col];
    g_Weff[i * HIDDEN + col] = acc;
}

// ---------------- promo offsets (full-precision HS) ------------------------
__global__ void promo_kernel(const float* __restrict__ HS) {
    int b = blockIdx.x;
    int tid = threadIdx.x;
    int lane = tid & 31, w = tid >> 5;
    for (int p = w; p < 24; p += 8) {
        int i = p >> 3;
        int s = p & 7;
        const float* h = HS + ((size_t)b * 64 + 48 + s) * HIDDEN;
        const float* we = g_Weff + i * HIDDEN;
        float acc = 0.f;
        for (int d = lane; d < HIDDEN; d += 32) acc += h[d] * we[d];
#pragma unroll
        for (int o = 16; o; o >>= 1) acc += __shfl_xor_sync(0xFFFFFFFFu, acc, o);
        if (lane == 0) g_PO[b * 24 + i * 8 + s] = acc;
    }
}

// ---------------- final sparse gather (board range) ------------------------
__global__ void gather_kernel(float* __restrict__ PL, const float* __restrict__ PAfull,
                              int b_off) {
    int c = blockIdx.x * blockDim.x + threadIdx.x;
    int b = b_off + blockIdx.y;
    if (c >= NCOLS) return;
    const float* pa = PAfull + (size_t)b * 4096;
    int n = g_cnt[c];
    float v = 0.f;
    for (int t = 0; t < n; t++) {
        int r = g_rows[c * 16 + t];
        if (r < 4096) {
            v += pa[r] * 0.125f;
        } else {
            int u = r - 4096;
            int r8 = u / 24, rem = u % 24;
            int cc = rem / 3, ii = rem % 3;
            v += pa[(48 + r8) * 64 + 56 + cc] + 8.0f * g_PO[b * 24 + ii * 8 + cc];
        }
    }
    PL[(size_t)b * NCOLS + c] = v;
}

// ---------------- launcher (3 streams, 12 nodes, 6 events) -----------------
extern "C" void kernel_launch(void* const* d_in, const int* in_sizes, int n_in,
                              void* d_out, int out_size) {
    const float* HS  = (const float*)d_in[0];
    const float* Wq  = (const float*)d_in[1];
    const float* Wk  = (const float*)d_in[2];
    const float* Wpk = (const float*)d_in[3];
    const float* Wpo = (const float*)d_in[4];
    const float* pm  = (const float*)d_in[5];
    int B = in_sizes[0] / (64 * HIDDEN);

    float* out = (float*)d_out;
    float* PL = out;
    float* PA = out + (size_t)B * NCOLS;

    static cudaStream_t s1 = nullptr, s2 = nullptr, s3 = nullptr;
    static cudaEvent_t e0 = nullptr, ev1 = nullptr, ev2 = nullptr;
    static cudaEvent_t ph0 = nullptr, ph1 = nullptr, eg1 = nullptr;
    if (!s1) {
        cudaStreamCreateWithFlags(&s1, cudaStreamNonBlocking);
        cudaStreamCreateWithFlags(&s2, cudaStreamNonBlocking);
        cudaStreamCreateWithFlags(&s3, cudaStreamNonBlocking);
        cudaEventCreateWithFlags(&e0, cudaEventDisableTiming);
        cudaEventCreateWithFlags(&ev1, cudaEventDisableTiming);
        cudaEventCreateWithFlags(&ev2, cudaEventDisableTiming);
        cudaEventCreateWithFlags(&ph0, cudaEventDisableTiming);
        cudaEventCreateWithFlags(&ph1, cudaEventDisableTiming);
        cudaEventCreateWithFlags(&eg1, cudaEventDisableTiming);
        cudaFuncSetAttribute(pass1_mma, cudaFuncAttributeMaxDynamicSharedMemorySize, P1_SMEMB);
    }

    int nblk = (B * 64) / 128;
    int blk1 = nblk < 296 ? (nblk + 1) / 2 : 296;
    int blk2 = nblk - blk1;
    int nb1 = blk1 * 2;                  // boards done after pass1_1
    int nb2 = B - nb1;

    // fork
    cudaEventRecord(e0, 0);
    cudaStreamWaitEvent(s1, e0, 0);
    cudaStreamWaitEvent(s2, e0, 0);
    cudaStreamWaitEvent(s3, e0, 0);

    // s1: colmap + weff + promo, then gather part 1 (after pass1_1 via eg1)
    build_colmap_seg<<<dim3((NCOLS + 255) / 256, NSEG), 256, 0, s1>>>(pm);
    merge_colmap<<<(NCOLS + 255) / 256, 256, 0, s1>>>();
    weff_kernel<<<dim3(3, 4), 256, 0, s1>>>(Wpo, Wpk);
    promo_kernel<<<B, 256, 0, s1>>>(HS);

    // s2: M = Wk^T Wq -> fp16 (split-K x16)
    gemm_tn_part<<<dim3(8, 8, 16), 256, 0, s2>>>(Wk, Wq);
    mh_combine<<<(HIDDEN * HIDDEN + 255) / 256, 256, 0, s2>>>();
    cudaEventRecord(ev2, s2);

    // s3: preround, asymmetric split
    int n4_1 = blk1 * 128 * (HIDDEN / 4);
    int n4_2 = blk2 * 128 * (HIDDEN / 4);
    preround_hs<<<(n4_1 + 255) / 256, 256, 0, s3>>>(HS, 0, n4_1);
    cudaEventRecord(ph0, s3);
    if (n4_2 > 0) preround_hs<<<(n4_2 + 255) / 256, 256, 0, s3>>>(HS, n4_1, n4_2);
    cudaEventRecord(ph1, s3);

    // main: fused pass1+pass2 halves
    cudaStreamWaitEvent(0, ev2, 0);
    cudaStreamWaitEvent(0, ph0, 0);
    pass1_mma<<<blk1, 256, P1_SMEMB>>>(PA, 0);
    cudaEventRecord(eg1, 0);
    cudaStreamWaitEvent(0, ph1, 0);
    if (blk2 > 0) pass1_mma<<<blk2, 256, P1_SMEMB>>>(PA, blk1);

    // s1: gather part 1 (boards 0..nb1) overlapped with pass1_2
    cudaStreamWaitEvent(s1, eg1, 0);
    gather_kernel<<<dim3((NCOLS + 255) / 256, nb1), 256, 0, s1>>>(PL, PA, 0);
    cudaEventRecord(ev1, s1);

    // main: gather part 2 (needs s1 complete for colmap/promo + gather1 done)
    cudaStreamWaitEvent(0, ev1, 0);
    if (nb2 > 0)
        gather_kernel<<<dim3((NCOLS + 255) / 256, nb2), 256>>>(PL, PA, nb1);
}